// round 11
// baseline (speedup 1.0000x reference)
#include <cuda_runtime.h>
#include <cuda_fp16.h>
#include <math.h>

#define NN 50000
#define NE 800000
#define DIM 128
#define DOUT 64

// ---- scratch (device globals: allocation-free) ----
__device__ float  g_agg[NN * DIM];
__device__ float  g_h0[NN * DIM];
__device__ float  g_h1[NN * DIM];
__device__ __half g_x16[NN * DIM];
__device__ __half g_h016[NN * DIM];
__device__ __half g_P16[NN * DOUT];
__device__ float  g_R[NN * DOUT];
__device__ int    g_cnt[NN];
__device__ int    g_rowstart[NN + 1];
__device__ int    g_cursor[NN];
__device__ int    g_srcs[NE];
__device__ int    g_bsum[64];

// ---------------- tf32 helpers ----------------
__device__ __forceinline__ unsigned f2tf32(float f) {
    unsigned r;
    asm("cvt.rna.tf32.f32 %0, %1;" : "=r"(r) : "f"(f));
    return r;
}

__device__ __forceinline__ void mma_tf32(float d[4], const unsigned a[4], const unsigned b[2]) {
    asm("mma.sync.aligned.m16n8k8.row.col.f32.tf32.tf32.f32 "
        "{%0,%1,%2,%3}, {%4,%5,%6,%7}, {%8,%9}, {%0,%1,%2,%3};"
        : "+f"(d[0]), "+f"(d[1]), "+f"(d[2]), "+f"(d[3])
        : "r"(a[0]), "r"(a[1]), "r"(a[2]), "r"(a[3]), "r"(b[0]), "r"(b[1]));
}

// ---------------- CSR build ----------------
__global__ void k_zero_cnt(int n) {
    int i = blockIdx.x * blockDim.x + threadIdx.x;
    if (i < n) g_cnt[i] = 0;
}

__global__ void k_hist(const int* __restrict__ dst, int E) {
    int e = blockIdx.x * blockDim.x + threadIdx.x;
    if (e < E) atomicAdd(&g_cnt[dst[e]], 1);
}

__global__ void __launch_bounds__(1024) k_scan1(int n) {
    __shared__ int wsum[32];
    const int tid = threadIdx.x, lane = tid & 31, wid = tid >> 5;
    const int i = blockIdx.x * 1024 + tid;
    int v = (i < n) ? g_cnt[i] : 0;
    int incl = v;
    #pragma unroll
    for (int o = 1; o < 32; o <<= 1) {
        int t = __shfl_up_sync(0xffffffffu, incl, o);
        if (lane >= o) incl += t;
    }
    if (lane == 31) wsum[wid] = incl;
    __syncthreads();
    if (wid == 0) {
        int s = wsum[lane];
        #pragma unroll
        for (int o = 1; o < 32; o <<= 1) {
            int t = __shfl_up_sync(0xffffffffu, s, o);
            if (lane >= o) s += t;
        }
        wsum[lane] = s;
    }
    __syncthreads();
    int excl = (wid > 0 ? wsum[wid - 1] : 0) + incl - v;
    if (i < n) g_rowstart[i] = excl;
    if (tid == 0) g_bsum[blockIdx.x] = wsum[31];
}

__global__ void k_scan2(int nb, int n) {
    __shared__ int sv[64];
    const int tid = threadIdx.x;
    if (tid < nb) sv[tid] = g_bsum[tid];
    __syncthreads();
    if (tid == 0) {
        int run = 0;
        for (int i = 0; i < nb; i++) { int t = sv[i]; sv[i] = run; run += t; }
        g_rowstart[n] = run;
    }
    __syncthreads();
    if (tid < nb) g_bsum[tid] = sv[tid];
}

__global__ void __launch_bounds__(1024) k_scan3(int n) {
    const int i = blockIdx.x * 1024 + threadIdx.x;
    if (i < n) {
        int v = g_rowstart[i] + g_bsum[blockIdx.x];
        g_rowstart[i] = v;
        g_cursor[i]   = v;
    }
}

__global__ void k_scatter(const int* __restrict__ src, const int* __restrict__ dst, int E) {
    int e = blockIdx.x * blockDim.x + threadIdx.x;
    if (e < E) {
        int p = atomicAdd(&g_cursor[dst[e]], 1);
        g_srcs[p] = src[e];
    }
}

// ---------------- x -> fp16 mirror ----------------
__global__ void k_f2h(const float* __restrict__ in, __half* __restrict__ out, int count4) {
    int i = blockIdx.x * blockDim.x + threadIdx.x;
    if (i < count4) {
        float4 v = *(const float4*)(in + i * 4);
        __half2 h0 = __floats2half2_rn(v.x, v.y);
        __half2 h1 = __floats2half2_rn(v.z, v.w);
        uint2 u = make_uint2(*(unsigned*)&h0, *(unsigned*)&h1);
        *(uint2*)(out + i * 4) = u;
    }
}

// ---------------- mean aggregation over fp16 rows (warp per node, fp32 accum) ----------------
__global__ void k_agg16(const __half* __restrict__ in, float* __restrict__ outm, int n) {
    int w = (blockIdx.x * blockDim.x + threadIdx.x) >> 5;
    int lane = threadIdx.x & 31;
    if (w >= n) return;
    int rs = g_rowstart[w], re = g_rowstart[w + 1];
    float4 acc = make_float4(0.f, 0.f, 0.f, 0.f);
    for (int j = rs; j < re;) {
        int c = min(32, re - j);
        int s = (lane < c) ? g_srcs[j + lane] : 0;
        #pragma unroll 4
        for (int i = 0; i < c; i++) {
            int si = __shfl_sync(0xffffffffu, s, i);
            uint2 u = *(const uint2*)(in + (size_t)si * DIM + lane * 4);
            float2 f0 = __half22float2(*(__half2*)&u.x);
            float2 f1 = __half22float2(*(__half2*)&u.y);
            acc.x += f0.x; acc.y += f0.y; acc.z += f1.x; acc.w += f1.y;
        }
        j += c;
    }
    int deg = re - rs;
    float sc = deg > 0 ? 1.0f / (float)deg : 0.0f;
    acc.x *= sc; acc.y *= sc; acc.z *= sc; acc.w *= sc;
    *(float4*)(outm + (size_t)w * DIM + lane * 4) = acc;
}

// ---------------- tensor-core dual-GEMM + bias + relu (layers 0/1, 128->128) ----------------
#define WSTRIDE 136   // 128 + 8 pad: conflict-free B frags
#define ASTRIDE 136

__global__ void __launch_bounds__(256) k_gemm_relu(
    const float* __restrict__ A1, const float* __restrict__ A2,
    const float* __restrict__ Wl, const float* __restrict__ Wr,
    const float* __restrict__ bb, float* __restrict__ out,
    __half* __restrict__ out16, int n)
{
    extern __shared__ unsigned sm[];
    unsigned* sWl = sm;                         // 128 x 136
    unsigned* sWr = sWl + DIM * WSTRIDE;        // 128 x 136
    unsigned* sA1 = sWr + DIM * WSTRIDE;        // 64 x 136
    unsigned* sA2 = sA1 + 64 * ASTRIDE;         // 64 x 136
    const int tid = threadIdx.x;
    const int row0 = blockIdx.x * 64;

    for (int i = tid * 4; i < DIM * DIM; i += 1024) {
        int r = i >> 7, c = i & 127;
        float4 v = *(const float4*)(Wl + i);
        *(uint4*)(sWl + r * WSTRIDE + c) =
            make_uint4(f2tf32(v.x), f2tf32(v.y), f2tf32(v.z), f2tf32(v.w));
        v = *(const float4*)(Wr + i);
        *(uint4*)(sWr + r * WSTRIDE + c) =
            make_uint4(f2tf32(v.x), f2tf32(v.y), f2tf32(v.z), f2tf32(v.w));
    }
    for (int i = tid * 4; i < 64 * DIM; i += 1024) {
        int r = i >> 7, c = i & 127;
        int gr = row0 + r;
        float4 v1, v2;
        if (gr < n) {
            v1 = *(const float4*)(A1 + (size_t)gr * DIM + c);
            v2 = *(const float4*)(A2 + (size_t)gr * DIM + c);
        } else {
            v1 = make_float4(0.f, 0.f, 0.f, 0.f); v2 = v1;
        }
        *(uint4*)(sA1 + r * ASTRIDE + c) =
            make_uint4(f2tf32(v1.x), f2tf32(v1.y), f2tf32(v1.z), f2tf32(v1.w));
        *(uint4*)(sA2 + r * ASTRIDE + c) =
            make_uint4(f2tf32(v2.x), f2tf32(v2.y), f2tf32(v2.z), f2tf32(v2.w));
    }
    __syncthreads();

    const int w    = tid >> 5, lane = tid & 31;
    const int wrg  = w & 3;        // row group: 16 rows
    const int wcol = w >> 2;       // col group: 64 cols
    const int gID  = lane >> 2, tig = lane & 3;
    const int r0   = wrg * 16;

    float acc[8][4];
    #pragma unroll
    for (int i = 0; i < 8; i++)
        #pragma unroll
        for (int j = 0; j < 4; j++) acc[i][j] = 0.f;

    #pragma unroll
    for (int kt = 0; kt < 16; kt++) {
        const int k0 = kt * 8;
        unsigned a1[4], a2[4];
        a1[0] = sA1[(r0 + gID)     * ASTRIDE + k0 + tig];
        a1[1] = sA1[(r0 + gID + 8) * ASTRIDE + k0 + tig];
        a1[2] = sA1[(r0 + gID)     * ASTRIDE + k0 + tig + 4];
        a1[3] = sA1[(r0 + gID + 8) * ASTRIDE + k0 + tig + 4];
        a2[0] = sA2[(r0 + gID)     * ASTRIDE + k0 + tig];
        a2[1] = sA2[(r0 + gID + 8) * ASTRIDE + k0 + tig];
        a2[2] = sA2[(r0 + gID)     * ASTRIDE + k0 + tig + 4];
        a2[3] = sA2[(r0 + gID + 8) * ASTRIDE + k0 + tig + 4];
        #pragma unroll
        for (int nt = 0; nt < 8; nt++) {
            const int n0 = wcol * 64 + nt * 8;
            unsigned b[2];
            b[0] = sWl[(k0 + tig)     * WSTRIDE + n0 + gID];
            b[1] = sWl[(k0 + tig + 4) * WSTRIDE + n0 + gID];
            mma_tf32(acc[nt], a1, b);
            b[0] = sWr[(k0 + tig)     * WSTRIDE + n0 + gID];
            b[1] = sWr[(k0 + tig + 4) * WSTRIDE + n0 + gID];
            mma_tf32(acc[nt], a2, b);
        }
    }

    #pragma unroll
    for (int nt = 0; nt < 8; nt++) {
        const int col = wcol * 64 + nt * 8 + 2 * tig;
        const float bi0 = bb[col], bi1 = bb[col + 1];
        int gr = row0 + r0 + gID;
        if (gr < n) {
            float2 o = make_float2(fmaxf(acc[nt][0] + bi0, 0.f),
                                   fmaxf(acc[nt][1] + bi1, 0.f));
            *(float2*)(out + (size_t)gr * DIM + col) = o;
            if (out16) {
                __half2 h = __floats2half2_rn(o.x, o.y);
                *(unsigned*)(out16 + (size_t)gr * DIM + col) = *(unsigned*)&h;
            }
        }
        gr += 8;
        if (gr < n) {
            float2 o = make_float2(fmaxf(acc[nt][2] + bi0, 0.f),
                                   fmaxf(acc[nt][3] + bi1, 0.f));
            *(float2*)(out + (size_t)gr * DIM + col) = o;
            if (out16) {
                __half2 h = __floats2half2_rn(o.x, o.y);
                *(unsigned*)(out16 + (size_t)gr * DIM + col) = *(unsigned*)&h;
            }
        }
    }
}

// ---------------- layer-2 pre-transform: P16 = A@Wl2 (fp16), R = A@Wr2 + b2 ----------------
#define W2STRIDE 72   // 64 + 8 pad

__global__ void __launch_bounds__(256) k_gemm_pre(
    const float* __restrict__ A,
    const float* __restrict__ Wl, const float* __restrict__ Wr,
    const float* __restrict__ bb,
    __half* __restrict__ P16, float* __restrict__ R, int n)
{
    extern __shared__ unsigned sm[];
    unsigned* sWl = sm;                          // 128 x 72
    unsigned* sWr = sWl + DIM * W2STRIDE;        // 128 x 72
    unsigned* sA  = sWr + DIM * W2STRIDE;        // 64 x 136
    const int tid = threadIdx.x;
    const int row0 = blockIdx.x * 64;

    for (int i = tid * 4; i < DIM * DOUT; i += 1024) {
        int r = i >> 6, c = i & 63;
        float4 v = *(const float4*)(Wl + i);
        *(uint4*)(sWl + r * W2STRIDE + c) =
            make_uint4(f2tf32(v.x), f2tf32(v.y), f2tf32(v.z), f2tf32(v.w));
        v = *(const float4*)(Wr + i);
        *(uint4*)(sWr + r * W2STRIDE + c) =
            make_uint4(f2tf32(v.x), f2tf32(v.y), f2tf32(v.z), f2tf32(v.w));
    }
    for (int i = tid * 4; i < 64 * DIM; i += 1024) {
        int r = i >> 7, c = i & 127;
        int gr = row0 + r;
        float4 v = (gr < n) ? *(const float4*)(A + (size_t)gr * DIM + c)
                            : make_float4(0.f, 0.f, 0.f, 0.f);
        *(uint4*)(sA + r * ASTRIDE + c) =
            make_uint4(f2tf32(v.x), f2tf32(v.y), f2tf32(v.z), f2tf32(v.w));
    }
    __syncthreads();

    const int w    = tid >> 5, lane = tid & 31;
    const int wrg  = w & 3;
    const int wcol = w >> 2;      // 2 groups of 32 cols
    const int gID  = lane >> 2, tig = lane & 3;
    const int r0   = wrg * 16;

    float accP[4][4], accR[4][4];
    #pragma unroll
    for (int i = 0; i < 4; i++)
        #pragma unroll
        for (int j = 0; j < 4; j++) { accP[i][j] = 0.f; accR[i][j] = 0.f; }

    #pragma unroll
    for (int kt = 0; kt < 16; kt++) {
        const int k0 = kt * 8;
        unsigned a[4];
        a[0] = sA[(r0 + gID)     * ASTRIDE + k0 + tig];
        a[1] = sA[(r0 + gID + 8) * ASTRIDE + k0 + tig];
        a[2] = sA[(r0 + gID)     * ASTRIDE + k0 + tig + 4];
        a[3] = sA[(r0 + gID + 8) * ASTRIDE + k0 + tig + 4];
        #pragma unroll
        for (int nt = 0; nt < 4; nt++) {
            const int n0 = wcol * 32 + nt * 8;
            unsigned b[2];
            b[0] = sWl[(k0 + tig)     * W2STRIDE + n0 + gID];
            b[1] = sWl[(k0 + tig + 4) * W2STRIDE + n0 + gID];
            mma_tf32(accP[nt], a, b);
            b[0] = sWr[(k0 + tig)     * W2STRIDE + n0 + gID];
            b[1] = sWr[(k0 + tig + 4) * W2STRIDE + n0 + gID];
            mma_tf32(accR[nt], a, b);
        }
    }

    #pragma unroll
    for (int nt = 0; nt < 4; nt++) {
        const int col = wcol * 32 + nt * 8 + 2 * tig;
        const float bi0 = bb[col], bi1 = bb[col + 1];
        int gr = row0 + r0 + gID;
        if (gr < n) {
            __half2 hp = __floats2half2_rn(accP[nt][0], accP[nt][1]);
            *(unsigned*)(P16 + (size_t)gr * DOUT + col) = *(unsigned*)&hp;
            *(float2*)(R + (size_t)gr * DOUT + col) = make_float2(accR[nt][0] + bi0, accR[nt][1] + bi1);
        }
        gr += 8;
        if (gr < n) {
            __half2 hp = __floats2half2_rn(accP[nt][2], accP[nt][3]);
            *(unsigned*)(P16 + (size_t)gr * DOUT + col) = *(unsigned*)&hp;
            *(float2*)(R + (size_t)gr * DOUT + col) = make_float2(accR[nt][2] + bi0, accR[nt][3] + bi1);
        }
    }
}

// ---------------- final: gather-mean P16 (64-wide) + R + log_softmax ----------------
__global__ void __launch_bounds__(256) k_final_agg(
    const __half* __restrict__ P16, const float* __restrict__ R,
    float* __restrict__ out_ls, float* __restrict__ out_h, int n)
{
    const int w = (blockIdx.x * blockDim.x + threadIdx.x) >> 5;
    const int lane = threadIdx.x & 31;
    if (w >= n) return;
    const int rs = g_rowstart[w], re = g_rowstart[w + 1];
    float a0 = 0.f, a1 = 0.f;
    for (int j = rs; j < re;) {
        int c = min(32, re - j);
        int s = (lane < c) ? g_srcs[j + lane] : 0;
        #pragma unroll 8
        for (int i = 0; i < c; i++) {
            int si = __shfl_sync(0xffffffffu, s, i);
            unsigned u = *(const unsigned*)(P16 + (size_t)si * DOUT + lane * 2);
            float2 v = __half22float2(*(__half2*)&u);
            a0 += v.x; a1 += v.y;
        }
        j += c;
    }
    const int deg = re - rs;
    const float sc = deg > 0 ? 1.0f / (float)deg : 0.0f;
    const float2 rv = *(const float2*)(R + (size_t)w * DOUT + lane * 2);
    a0 = a0 * sc + rv.x;
    a1 = a1 * sc + rv.y;

    float m = fmaxf(a0, a1);
    #pragma unroll
    for (int o = 1; o < 32; o <<= 1)
        m = fmaxf(m, __shfl_xor_sync(0xffffffffu, m, o));
    float s = expf(a0 - m) + expf(a1 - m);
    #pragma unroll
    for (int o = 1; o < 32; o <<= 1)
        s += __shfl_xor_sync(0xffffffffu, s, o);
    const float lse = m + logf(s);

    *(float2*)(out_ls + (size_t)w * DOUT + lane * 2) = make_float2(a0 - lse, a1 - lse);
    if (out_h)
        *(float2*)(out_h + (size_t)w * DOUT + lane * 2) = make_float2(a0, a1);
}

// ---------------- driver ----------------
extern "C" void kernel_launch(void* const* d_in, const int* in_sizes, int n_in,
                              void* d_out, int out_size) {
    const float* x   = (const float*)d_in[0];
    const int*   ei  = (const int*)d_in[1];
    const float* Wl0 = (const float*)d_in[2];
    const float* Wr0 = (const float*)d_in[3];
    const float* b0  = (const float*)d_in[4];
    const float* Wl1 = (const float*)d_in[5];
    const float* Wr1 = (const float*)d_in[6];
    const float* b1  = (const float*)d_in[7];
    const float* Wl2 = (const float*)d_in[8];
    const float* Wr2 = (const float*)d_in[9];
    const float* b2  = (const float*)d_in[10];

    int n = in_sizes[0] / DIM;   // 50000
    int E = in_sizes[1] / 2;     // 800000
    const int* src = ei;
    const int* dst = ei + E;

    float *agg, *h0, *h1, *R;
    __half *x16, *h016, *P16;
    cudaGetSymbolAddress((void**)&agg,  g_agg);
    cudaGetSymbolAddress((void**)&h0,   g_h0);
    cudaGetSymbolAddress((void**)&h1,   g_h1);
    cudaGetSymbolAddress((void**)&R,    g_R);
    cudaGetSymbolAddress((void**)&x16,  g_x16);
    cudaGetSymbolAddress((void**)&h016, g_h016);
    cudaGetSymbolAddress((void**)&P16,  g_P16);

    float* out_ls = (float*)d_out;
    float* out_h  = (out_size >= 2 * n * DOUT) ? out_ls + (size_t)n * DOUT : nullptr;

    // CSR build
    const int nb = (n + 1023) / 1024;
    k_zero_cnt<<<(n + 255) / 256, 256>>>(n);
    k_hist<<<(E + 255) / 256, 256>>>(dst, E);
    k_scan1<<<nb, 1024>>>(n);
    k_scan2<<<1, 64>>>(nb, n);
    k_scan3<<<nb, 1024>>>(n);
    k_scatter<<<(E + 255) / 256, 256>>>(src, dst, E);

    // fp16 mirror of x
    const int c4 = n * DIM / 4;
    k_f2h<<<(c4 + 255) / 256, 256>>>(x, x16, c4);

    const int aggBlocks  = (n * 32 + 255) / 256;
    const int gemmBlocks = (n + 63) / 64;
    const size_t smemRelu = (size_t)(2 * DIM * WSTRIDE + 2 * 64 * ASTRIDE) * 4;   // 208896
    const size_t smemPre  = (size_t)(2 * DIM * W2STRIDE + 64 * ASTRIDE) * 4;      // 108544
    cudaFuncSetAttribute(k_gemm_relu, cudaFuncAttributeMaxDynamicSharedMemorySize, (int)smemRelu);
    cudaFuncSetAttribute(k_gemm_pre,  cudaFuncAttributeMaxDynamicSharedMemorySize, (int)smemPre);

    // layer 0 (gather fp16 x; emit h0 fp32 + fp16 mirror)
    k_agg16<<<aggBlocks, 256>>>(x16, agg, n);
    k_gemm_relu<<<gemmBlocks, 256, smemRelu>>>(agg, x, Wl0, Wr0, b0, h0, h016, n);
    // layer 1 (gather fp16 h0)
    k_agg16<<<aggBlocks, 256>>>(h016, agg, n);
    k_gemm_relu<<<gemmBlocks, 256, smemRelu>>>(agg, h0, Wl1, Wr1, b1, h1, (__half*)nullptr, n);
    // layer 2: transform, then aggregate in 64-dim fp16 space + log_softmax
    k_gemm_pre<<<gemmBlocks, 256, smemPre>>>(h1, Wl2, Wr2, b2, P16, R, n);
    k_final_agg<<<aggBlocks, 256>>>(P16, R, out_ls, out_h, n);
}

// round 13
// speedup vs baseline: 1.0687x; 1.0687x over previous
#include <cuda_runtime.h>
#include <math.h>

#define NN 50000
#define NE 800000
#define DIM 128
#define DOUT 64

// ---- scratch (device globals: allocation-free) ----
__device__ float g_agg[NN * DIM];
__device__ float g_h0[NN * DIM];
__device__ float g_h1[NN * DIM];
__device__ float g_P[NN * DOUT];
__device__ float g_R[NN * DOUT];
__device__ int   g_cnt[NN];
__device__ int   g_rowstart[NN + 1];
__device__ int   g_rank[NE];
__device__ int   g_srcs[NE];
__device__ int   g_bsum[64];

// ---------------- tf32 helpers ----------------
__device__ __forceinline__ unsigned f2tf32(float f) {
    unsigned r;
    asm("cvt.rna.tf32.f32 %0, %1;" : "=r"(r) : "f"(f));
    return r;
}

__device__ __forceinline__ void mma_tf32(float d[4], const unsigned a[4], const unsigned b[2]) {
    asm("mma.sync.aligned.m16n8k8.row.col.f32.tf32.tf32.f32 "
        "{%0,%1,%2,%3}, {%4,%5,%6,%7}, {%8,%9}, {%0,%1,%2,%3};"
        : "+f"(d[0]), "+f"(d[1]), "+f"(d[2]), "+f"(d[3])
        : "r"(a[0]), "r"(a[1]), "r"(a[2]), "r"(a[3]), "r"(b[0]), "r"(b[1]));
}

// ---------------- CSR build ----------------
// hist + per-edge rank (the atomic's return value IS the rank)
__global__ void k_hist(const int* __restrict__ dst, int E) {
    int e = blockIdx.x * blockDim.x + threadIdx.x;
    if (e < E) g_rank[e] = atomicAdd(&g_cnt[dst[e]], 1);
}

__global__ void __launch_bounds__(1024) k_scan1(int n) {
    __shared__ int wsum[32];
    const int tid = threadIdx.x, lane = tid & 31, wid = tid >> 5;
    const int i = blockIdx.x * 1024 + tid;
    int v = (i < n) ? g_cnt[i] : 0;
    int incl = v;
    #pragma unroll
    for (int o = 1; o < 32; o <<= 1) {
        int t = __shfl_up_sync(0xffffffffu, incl, o);
        if (lane >= o) incl += t;
    }
    if (lane == 31) wsum[wid] = incl;
    __syncthreads();
    if (wid == 0) {
        int s = wsum[lane];
        #pragma unroll
        for (int o = 1; o < 32; o <<= 1) {
            int t = __shfl_up_sync(0xffffffffu, s, o);
            if (lane >= o) s += t;
        }
        wsum[lane] = s;
    }
    __syncthreads();
    int excl = (wid > 0 ? wsum[wid - 1] : 0) + incl - v;
    if (i < n) g_rowstart[i] = excl;
    if (tid == 0) g_bsum[blockIdx.x] = wsum[31];
}

// one-warp shuffle scan over up to 64 block totals
__global__ void k_scan2(int nb, int n) {
    const int lane = threadIdx.x;
    int v0 = (lane < nb)      ? g_bsum[lane]      : 0;
    int v1 = (lane + 32 < nb) ? g_bsum[lane + 32] : 0;
    int s0 = v0, s1 = v1;
    #pragma unroll
    for (int o = 1; o < 32; o <<= 1) {
        int t0 = __shfl_up_sync(0xffffffffu, s0, o);
        int t1 = __shfl_up_sync(0xffffffffu, s1, o);
        if (lane >= o) { s0 += t0; s1 += t1; }
    }
    const int tot0 = __shfl_sync(0xffffffffu, s0, 31);
    const int tot1 = __shfl_sync(0xffffffffu, s1, 31);
    if (lane < nb)      g_bsum[lane]      = s0 - v0;
    if (lane + 32 < nb) g_bsum[lane + 32] = tot0 + s1 - v1;
    if (lane == 0) g_rowstart[n] = tot0 + tot1;
}

__global__ void __launch_bounds__(1024) k_scan3(int n) {
    const int i = blockIdx.x * 1024 + threadIdx.x;
    if (i < n) g_rowstart[i] += g_bsum[blockIdx.x];
}

// atomic-free scatter using precomputed ranks
__global__ void k_scatter(const int* __restrict__ src, const int* __restrict__ dst, int E) {
    int e = blockIdx.x * blockDim.x + threadIdx.x;
    if (e < E)
        g_srcs[g_rowstart[dst[e]] + g_rank[e]] = src[e];
}

// ---------------- mean aggregation (pull, warp per node, high occupancy) ----------------
__global__ void k_agg(const float* __restrict__ in, float* __restrict__ outm, int n) {
    int w = (blockIdx.x * blockDim.x + threadIdx.x) >> 5;
    int lane = threadIdx.x & 31;
    if (w >= n) return;
    int rs = g_rowstart[w], re = g_rowstart[w + 1];
    float4 acc = make_float4(0.f, 0.f, 0.f, 0.f);
    for (int j = rs; j < re;) {
        int c = min(32, re - j);
        int s = (lane < c) ? g_srcs[j + lane] : 0;
        #pragma unroll 4
        for (int i = 0; i < c; i++) {
            int si = __shfl_sync(0xffffffffu, s, i);
            float4 v = *(const float4*)(in + (size_t)si * DIM + lane * 4);
            acc.x += v.x; acc.y += v.y; acc.z += v.z; acc.w += v.w;
        }
        j += c;
    }
    int deg = re - rs;
    float sc = deg > 0 ? 1.0f / (float)deg : 0.0f;
    acc.x *= sc; acc.y *= sc; acc.z *= sc; acc.w *= sc;
    *(float4*)(outm + (size_t)w * DIM + lane * 4) = acc;
}

// ---------------- tensor-core dual-GEMM + bias + relu (layers 0/1, 128->128) ----------------
#define WSTRIDE 136   // 128 + 8 pad: conflict-free B frags
#define ASTRIDE 136

__global__ void __launch_bounds__(256) k_gemm_relu(
    const float* __restrict__ A1, const float* __restrict__ A2,
    const float* __restrict__ Wl, const float* __restrict__ Wr,
    const float* __restrict__ bb, float* __restrict__ out, int n)
{
    extern __shared__ unsigned sm[];
    unsigned* sWl = sm;                         // 128 x 136
    unsigned* sWr = sWl + DIM * WSTRIDE;        // 128 x 136
    unsigned* sA1 = sWr + DIM * WSTRIDE;        // 64 x 136
    unsigned* sA2 = sA1 + 64 * ASTRIDE;         // 64 x 136
    const int tid = threadIdx.x;
    const int row0 = blockIdx.x * 64;

    for (int i = tid * 4; i < DIM * DIM; i += 1024) {
        int r = i >> 7, c = i & 127;
        float4 v = *(const float4*)(Wl + i);
        *(uint4*)(sWl + r * WSTRIDE + c) =
            make_uint4(f2tf32(v.x), f2tf32(v.y), f2tf32(v.z), f2tf32(v.w));
        v = *(const float4*)(Wr + i);
        *(uint4*)(sWr + r * WSTRIDE + c) =
            make_uint4(f2tf32(v.x), f2tf32(v.y), f2tf32(v.z), f2tf32(v.w));
    }
    for (int i = tid * 4; i < 64 * DIM; i += 1024) {
        int r = i >> 7, c = i & 127;
        int gr = row0 + r;
        float4 v1, v2;
        if (gr < n) {
            v1 = *(const float4*)(A1 + (size_t)gr * DIM + c);
            v2 = *(const float4*)(A2 + (size_t)gr * DIM + c);
        } else {
            v1 = make_float4(0.f, 0.f, 0.f, 0.f); v2 = v1;
        }
        *(uint4*)(sA1 + r * ASTRIDE + c) =
            make_uint4(f2tf32(v1.x), f2tf32(v1.y), f2tf32(v1.z), f2tf32(v1.w));
        *(uint4*)(sA2 + r * ASTRIDE + c) =
            make_uint4(f2tf32(v2.x), f2tf32(v2.y), f2tf32(v2.z), f2tf32(v2.w));
    }
    __syncthreads();

    const int w    = tid >> 5, lane = tid & 31;
    const int wrg  = w & 3;        // row group: 16 rows
    const int wcol = w >> 2;       // col group: 64 cols
    const int gID  = lane >> 2, tig = lane & 3;
    const int r0   = wrg * 16;

    float acc[8][4];
    #pragma unroll
    for (int i = 0; i < 8; i++)
        #pragma unroll
        for (int j = 0; j < 4; j++) acc[i][j] = 0.f;

    #pragma unroll
    for (int kt = 0; kt < 16; kt++) {
        const int k0 = kt * 8;
        unsigned a1[4], a2[4];
        a1[0] = sA1[(r0 + gID)     * ASTRIDE + k0 + tig];
        a1[1] = sA1[(r0 + gID + 8) * ASTRIDE + k0 + tig];
        a1[2] = sA1[(r0 + gID)     * ASTRIDE + k0 + tig + 4];
        a1[3] = sA1[(r0 + gID + 8) * ASTRIDE + k0 + tig + 4];
        a2[0] = sA2[(r0 + gID)     * ASTRIDE + k0 + tig];
        a2[1] = sA2[(r0 + gID + 8) * ASTRIDE + k0 + tig];
        a2[2] = sA2[(r0 + gID)     * ASTRIDE + k0 + tig + 4];
        a2[3] = sA2[(r0 + gID + 8) * ASTRIDE + k0 + tig + 4];
        #pragma unroll
        for (int nt = 0; nt < 8; nt++) {
            const int n0 = wcol * 64 + nt * 8;
            unsigned b[2];
            b[0] = sWl[(k0 + tig)     * WSTRIDE + n0 + gID];
            b[1] = sWl[(k0 + tig + 4) * WSTRIDE + n0 + gID];
            mma_tf32(acc[nt], a1, b);
            b[0] = sWr[(k0 + tig)     * WSTRIDE + n0 + gID];
            b[1] = sWr[(k0 + tig + 4) * WSTRIDE + n0 + gID];
            mma_tf32(acc[nt], a2, b);
        }
    }

    #pragma unroll
    for (int nt = 0; nt < 8; nt++) {
        const int col = wcol * 64 + nt * 8 + 2 * tig;
        const float bi0 = bb[col], bi1 = bb[col + 1];
        int gr = row0 + r0 + gID;
        if (gr < n) {
            float2 o = make_float2(fmaxf(acc[nt][0] + bi0, 0.f),
                                   fmaxf(acc[nt][1] + bi1, 0.f));
            *(float2*)(out + (size_t)gr * DIM + col) = o;
        }
        gr += 8;
        if (gr < n) {
            float2 o = make_float2(fmaxf(acc[nt][2] + bi0, 0.f),
                                   fmaxf(acc[nt][3] + bi1, 0.f));
            *(float2*)(out + (size_t)gr * DIM + col) = o;
        }
    }
}

// ---------------- layer-2 pre-transform: P = A@Wl2, R = A@Wr2 + b2 ----------------
#define W2STRIDE 72   // 64 + 8 pad

__global__ void __launch_bounds__(256) k_gemm_pre(
    const float* __restrict__ A,
    const float* __restrict__ Wl, const float* __restrict__ Wr,
    const float* __restrict__ bb,
    float* __restrict__ P, float* __restrict__ R, int n)
{
    extern __shared__ unsigned sm[];
    unsigned* sWl = sm;                          // 128 x 72
    unsigned* sWr = sWl + DIM * W2STRIDE;        // 128 x 72
    unsigned* sA  = sWr + DIM * W2STRIDE;        // 64 x 136
    const int tid = threadIdx.x;
    const int row0 = blockIdx.x * 64;

    for (int i = tid * 4; i < DIM * DOUT; i += 1024) {
        int r = i >> 6, c = i & 63;
        float4 v = *(const float4*)(Wl + i);
        *(uint4*)(sWl + r * W2STRIDE + c) =
            make_uint4(f2tf32(v.x), f2tf32(v.y), f2tf32(v.z), f2tf32(v.w));
        v = *(const float4*)(Wr + i);
        *(uint4*)(sWr + r * W2STRIDE + c) =
            make_uint4(f2tf32(v.x), f2tf32(v.y), f2tf32(v.z), f2tf32(v.w));
    }
    for (int i = tid * 4; i < 64 * DIM; i += 1024) {
        int r = i >> 7, c = i & 127;
        int gr = row0 + r;
        float4 v = (gr < n) ? *(const float4*)(A + (size_t)gr * DIM + c)
                            : make_float4(0.f, 0.f, 0.f, 0.f);
        *(uint4*)(sA + r * ASTRIDE + c) =
            make_uint4(f2tf32(v.x), f2tf32(v.y), f2tf32(v.z), f2tf32(v.w));
    }
    __syncthreads();

    const int w    = tid >> 5, lane = tid & 31;
    const int wrg  = w & 3;
    const int wcol = w >> 2;      // 2 groups of 32 cols
    const int gID  = lane >> 2, tig = lane & 3;
    const int r0   = wrg * 16;

    float accP[4][4], accR[4][4];
    #pragma unroll
    for (int i = 0; i < 4; i++)
        #pragma unroll
        for (int j = 0; j < 4; j++) { accP[i][j] = 0.f; accR[i][j] = 0.f; }

    #pragma unroll
    for (int kt = 0; kt < 16; kt++) {
        const int k0 = kt * 8;
        unsigned a[4];
        a[0] = sA[(r0 + gID)     * ASTRIDE + k0 + tig];
        a[1] = sA[(r0 + gID + 8) * ASTRIDE + k0 + tig];
        a[2] = sA[(r0 + gID)     * ASTRIDE + k0 + tig + 4];
        a[3] = sA[(r0 + gID + 8) * ASTRIDE + k0 + tig + 4];
        #pragma unroll
        for (int nt = 0; nt < 4; nt++) {
            const int n0 = wcol * 32 + nt * 8;
            unsigned b[2];
            b[0] = sWl[(k0 + tig)     * W2STRIDE + n0 + gID];
            b[1] = sWl[(k0 + tig + 4) * W2STRIDE + n0 + gID];
            mma_tf32(accP[nt], a, b);
            b[0] = sWr[(k0 + tig)     * W2STRIDE + n0 + gID];
            b[1] = sWr[(k0 + tig + 4) * W2STRIDE + n0 + gID];
            mma_tf32(accR[nt], a, b);
        }
    }

    #pragma unroll
    for (int nt = 0; nt < 4; nt++) {
        const int col = wcol * 32 + nt * 8 + 2 * tig;
        const float bi0 = bb[col], bi1 = bb[col + 1];
        int gr = row0 + r0 + gID;
        if (gr < n) {
            *(float2*)(P + (size_t)gr * DOUT + col) = make_float2(accP[nt][0], accP[nt][1]);
            *(float2*)(R + (size_t)gr * DOUT + col) = make_float2(accR[nt][0] + bi0, accR[nt][1] + bi1);
        }
        gr += 8;
        if (gr < n) {
            *(float2*)(P + (size_t)gr * DOUT + col) = make_float2(accP[nt][2], accP[nt][3]);
            *(float2*)(R + (size_t)gr * DOUT + col) = make_float2(accR[nt][2] + bi0, accR[nt][3] + bi1);
        }
    }
}

// ---------------- final: gather-mean P (64-wide) + R + log_softmax ----------------
__global__ void __launch_bounds__(256) k_final_agg(
    const float* __restrict__ P, const float* __restrict__ R,
    float* __restrict__ out_ls, float* __restrict__ out_h, int n)
{
    const int w = (blockIdx.x * blockDim.x + threadIdx.x) >> 5;
    const int lane = threadIdx.x & 31;
    if (w >= n) return;
    const int rs = g_rowstart[w], re = g_rowstart[w + 1];
    float a0 = 0.f, a1 = 0.f;
    for (int j = rs; j < re;) {
        int c = min(32, re - j);
        int s = (lane < c) ? g_srcs[j + lane] : 0;
        #pragma unroll 8
        for (int i = 0; i < c; i++) {
            int si = __shfl_sync(0xffffffffu, s, i);
            const float2 v = *(const float2*)(P + (size_t)si * DOUT + lane * 2);
            a0 += v.x; a1 += v.y;
        }
        j += c;
    }
    const int deg = re - rs;
    const float sc = deg > 0 ? 1.0f / (float)deg : 0.0f;
    const float2 rv = *(const float2*)(R + (size_t)w * DOUT + lane * 2);
    a0 = a0 * sc + rv.x;
    a1 = a1 * sc + rv.y;

    float m = fmaxf(a0, a1);
    #pragma unroll
    for (int o = 1; o < 32; o <<= 1)
        m = fmaxf(m, __shfl_xor_sync(0xffffffffu, m, o));
    float s = expf(a0 - m) + expf(a1 - m);
    #pragma unroll
    for (int o = 1; o < 32; o <<= 1)
        s += __shfl_xor_sync(0xffffffffu, s, o);
    const float lse = m + logf(s);

    *(float2*)(out_ls + (size_t)w * DOUT + lane * 2) = make_float2(a0 - lse, a1 - lse);
    if (out_h)
        *(float2*)(out_h + (size_t)w * DOUT + lane * 2) = make_float2(a0, a1);
}

// ---------------- driver ----------------
extern "C" void kernel_launch(void* const* d_in, const int* in_sizes, int n_in,
                              void* d_out, int out_size) {
    const float* x   = (const float*)d_in[0];
    const int*   ei  = (const int*)d_in[1];
    const float* Wl0 = (const float*)d_in[2];
    const float* Wr0 = (const float*)d_in[3];
    const float* b0  = (const float*)d_in[4];
    const float* Wl1 = (const float*)d_in[5];
    const float* Wr1 = (const float*)d_in[6];
    const float* b1  = (const float*)d_in[7];
    const float* Wl2 = (const float*)d_in[8];
    const float* Wr2 = (const float*)d_in[9];
    const float* b2  = (const float*)d_in[10];

    int n = in_sizes[0] / DIM;   // 50000
    int E = in_sizes[1] / 2;     // 800000
    const int* src = ei;
    const int* dst = ei + E;

    float *agg, *h0, *h1, *P, *R;
    int *cnt;
    cudaGetSymbolAddress((void**)&agg, g_agg);
    cudaGetSymbolAddress((void**)&h0,  g_h0);
    cudaGetSymbolAddress((void**)&h1,  g_h1);
    cudaGetSymbolAddress((void**)&P,   g_P);
    cudaGetSymbolAddress((void**)&R,   g_R);
    cudaGetSymbolAddress((void**)&cnt, g_cnt);

    float* out_ls = (float*)d_out;
    float* out_h  = (out_size >= 2 * n * DOUT) ? out_ls + (size_t)n * DOUT : nullptr;

    // CSR build (atomic-free scatter via hist ranks)
    const int nb = (n + 1023) / 1024;
    cudaMemsetAsync(cnt, 0, (size_t)n * sizeof(int));
    k_hist<<<(E + 255) / 256, 256>>>(dst, E);
    k_scan1<<<nb, 1024>>>(n);
    k_scan2<<<1, 32>>>(nb, n);
    k_scan3<<<nb, 1024>>>(n);
    k_scatter<<<(E + 255) / 256, 256>>>(src, dst, E);

    const int aggBlocks  = (n * 32 + 255) / 256;
    const int gemmBlocks = (n + 63) / 64;
    const size_t smemRelu = (size_t)(2 * DIM * WSTRIDE + 2 * 64 * ASTRIDE) * 4;   // 208896
    const size_t smemPre  = (size_t)(2 * DIM * W2STRIDE + 64 * ASTRIDE) * 4;      // 108544
    cudaFuncSetAttribute(k_gemm_relu, cudaFuncAttributeMaxDynamicSharedMemorySize, (int)smemRelu);
    cudaFuncSetAttribute(k_gemm_pre,  cudaFuncAttributeMaxDynamicSharedMemorySize, (int)smemPre);

    // layer 0
    k_agg<<<aggBlocks, 256>>>(x, agg, n);
    k_gemm_relu<<<gemmBlocks, 256, smemRelu>>>(agg, x, Wl0, Wr0, b0, h0, n);
    // layer 1
    k_agg<<<aggBlocks, 256>>>(h0, agg, n);
    k_gemm_relu<<<gemmBlocks, 256, smemRelu>>>(agg, h0, Wl1, Wr1, b1, h1, n);
    // layer 2: transform, then aggregate in 64-dim space + log_softmax
    k_gemm_pre<<<gemmBlocks, 256, smemPre>>>(h1, Wl2, Wr2, b2, P, R, n);
    k_final_agg<<<aggBlocks, 256>>>(P, R, out_ls, out_h, n);
}